// round 6
// baseline (speedup 1.0000x reference)
#include <cuda_runtime.h>

#define FDIM 128
#define F2   16
#define NMAX 100000
#define EMAX 1600000
#define SCAN_TPB 1024
#define NBLK ((NMAX + SCAN_TPB - 1) / SCAN_TPB)   // 98
#define WS_STRIDE 136                              // W smem row stride (conflict-free B frags)

// ---- device scratch (static allocation; no cudaMalloc allowed) ----
__device__ float g_dinv[NMAX];                  // deg^{-1/2}
__device__ int   g_deg[NMAX];                   // in-degree histogram (per-launch zeroed)
__device__ int   g_rowstart[NMAX + 1];          // CSR row offsets (by dst)
__device__ int   g_cur[NMAX];                   // CSR fill cursors
__device__ int   g_csr[EMAX];                   // CSR column (src) indices
__device__ int   g_bsum[NBLK];                  // per-block degree sums
__device__ int   g_boff[NBLK];                  // exclusive block offsets
__device__ float g_h0[(size_t)NMAX * FDIM];     // raw x@W1 (no dinv)
__device__ float g_h1[(size_t)NMAX * FDIM];     // relu(aggregated layer 1)
__device__ float g_t2[(size_t)NMAX * F2];       // (h1@W2) * dinv[row]
__device__ int   g_idx64;                       // 1 if edge_index is int64, 0 if int32

// Flag-dispatched edge read (handles int64 vs int32 edge_index).
__device__ __forceinline__ int edge_at(const void* ei, long long i) {
    if (g_idx64) return (int)((const long long*)ei)[i];
    return ((const int*)ei)[i];
}

__device__ __forceinline__ unsigned f2tf32(float f) {
    unsigned r;
    asm("cvt.rna.tf32.f32 %0, %1;" : "=r"(r) : "f"(f));
    return r;
}

__device__ __forceinline__ void mma_tf32(float* d, unsigned a0, unsigned a1,
                                         unsigned a2, unsigned a3,
                                         unsigned b0, unsigned b1) {
    asm volatile(
        "mma.sync.aligned.m16n8k8.row.col.f32.tf32.tf32.f32 "
        "{%0,%1,%2,%3}, {%4,%5,%6,%7}, {%8,%9}, {%0,%1,%2,%3};"
        : "+f"(d[0]), "+f"(d[1]), "+f"(d[2]), "+f"(d[3])
        : "r"(a0), "r"(a1), "r"(a2), "r"(a3), "r"(b0), "r"(b1));
}

// ---- K1: zero the degree histogram; block 0 thread 0 also probes edge dtype.
// int64 indices < 1e5 -> high word always 0; int32 data reinterpreted as u64
// has a random index in the high word (nonzero w.p. 1-1e-5 per sample). ----
__global__ void zero_probe_k(const unsigned long long* __restrict__ ei, int n) {
    int i = blockIdx.x * blockDim.x + threadIdx.x;
    if (i < n) g_deg[i] = 0;
    if (i == 0) {
        int is64 = 1;
        for (int j = 0; j < 256; j++) {
            if (ei[j] >> 32) { is64 = 0; break; }
        }
        g_idx64 = is64;
    }
}

// ---- K2 (fused): blocks [0, gemm_blocks) compute g_h0 = x @ W1 via
// split-TF32 tensor-core MMA; remaining blocks do the in-degree histogram.
// The two jobs are fully independent -> true overlap without streams. ----
__global__ void __launch_bounds__(256) histgemm_k(
        const float* __restrict__ x, const float* __restrict__ W1,
        const void* __restrict__ ei, int n, int e, int gemm_blocks) {
    if (blockIdx.x >= gemm_blocks) {
        // --- histogram part ---
        long long b = blockIdx.x - gemm_blocks;
        long long t = b * blockDim.x + threadIdx.x;
        if (t < e) {
            int d = edge_at(ei, (long long)e + t);
            atomicAdd(&g_deg[d], 1);
        }
        return;
    }

    // --- GEMM part: block tile = 128 rows; warp tile = 16 rows x 128 cols.
    // Error-free-ish split: a = hi + lo (hi = tf32-round, lo exact residual),
    // D = Ahi*Bhi + Alo*Bhi + Ahi*Blo -> residual ~2^-22.
    extern __shared__ float Ws[];        // [128][WS_STRIDE]
    int tid = threadIdx.x;
    int warp = tid >> 5, lane = tid & 31;

    #pragma unroll
    for (int i = 0; i < 64; i++) {
        int idx = i * 256 + tid;         // 16384 elements of W1
        int k = idx >> 7, nn = idx & 127;
        Ws[k * WS_STRIDE + nn] = W1[idx];
    }
    __syncthreads();

    int r_base = blockIdx.x * 128 + warp * 16;
    int row_a = r_base + (lane >> 2);    // fragment row (lower 8)
    int quad  = lane & 3;

    float acc[16][4];
    #pragma unroll
    for (int nt = 0; nt < 16; nt++) {
        acc[nt][0] = acc[nt][1] = acc[nt][2] = acc[nt][3] = 0.0f;
    }

    #pragma unroll
    for (int ks = 0; ks < 16; ks++) {
        int k0 = ks * 8;
        float a0f = (row_a < n)     ? __ldg(&x[row_a * FDIM + k0 + quad])           : 0.0f;
        float a1f = (row_a + 8 < n) ? __ldg(&x[(row_a + 8) * FDIM + k0 + quad])     : 0.0f;
        float a2f = (row_a < n)     ? __ldg(&x[row_a * FDIM + k0 + 4 + quad])       : 0.0f;
        float a3f = (row_a + 8 < n) ? __ldg(&x[(row_a + 8) * FDIM + k0 + 4 + quad]) : 0.0f;
        unsigned ah0 = f2tf32(a0f), ah1 = f2tf32(a1f), ah2 = f2tf32(a2f), ah3 = f2tf32(a3f);
        unsigned al0 = f2tf32(a0f - __uint_as_float(ah0));
        unsigned al1 = f2tf32(a1f - __uint_as_float(ah1));
        unsigned al2 = f2tf32(a2f - __uint_as_float(ah2));
        unsigned al3 = f2tf32(a3f - __uint_as_float(ah3));

        const float* w0 = &Ws[(k0 + quad) * WS_STRIDE + (lane >> 2)];
        const float* w1 = &Ws[(k0 + 4 + quad) * WS_STRIDE + (lane >> 2)];
        #pragma unroll
        for (int nt = 0; nt < 16; nt++) {
            float b0f = w0[nt * 8];
            float b1f = w1[nt * 8];
            unsigned bh0 = f2tf32(b0f), bh1 = f2tf32(b1f);
            unsigned bl0 = f2tf32(b0f - __uint_as_float(bh0));
            unsigned bl1 = f2tf32(b1f - __uint_as_float(bh1));
            mma_tf32(acc[nt], ah0, ah1, ah2, ah3, bh0, bh1);
            mma_tf32(acc[nt], al0, al1, al2, al3, bh0, bh1);
            mma_tf32(acc[nt], ah0, ah1, ah2, ah3, bl0, bl1);
        }
    }

    // Epilogue: store raw (dinv applied later in pull1).
    #pragma unroll
    for (int nt = 0; nt < 16; nt++) {
        int col = nt * 8 + quad * 2;
        if (row_a < n) {
            float2 v = make_float2(acc[nt][0], acc[nt][1]);
            *(float2*)&g_h0[(size_t)row_a * FDIM + col] = v;
        }
        if (row_a + 8 < n) {
            float2 v = make_float2(acc[nt][2], acc[nt][3]);
            *(float2*)&g_h0[(size_t)(row_a + 8) * FDIM + col] = v;
        }
    }
}

// Block-wide inclusive scan of one value per thread (1024 threads, 32 warps).
__device__ __forceinline__ int block_scan_1024(int v, int* block_total, int* wsum) {
    int lane = threadIdx.x & 31, w = threadIdx.x >> 5;
    int x = v;
    #pragma unroll
    for (int o = 1; o < 32; o <<= 1) {
        int y = __shfl_up_sync(0xffffffffu, x, o);
        if (lane >= o) x += y;
    }
    if (lane == 31) wsum[w] = x;
    __syncthreads();
    if (w == 0) {
        int s = wsum[lane];
        #pragma unroll
        for (int o = 1; o < 32; o <<= 1) {
            int y = __shfl_up_sync(0xffffffffu, s, o);
            if (lane >= o) s += y;
        }
        wsum[lane] = s;
    }
    __syncthreads();
    int incl = x + (w > 0 ? wsum[w - 1] : 0);
    *block_total = wsum[31];
    return incl;
}

// ---- K3a: per-block degree sums ----
__global__ void scan_phase1_k(int n) {
    __shared__ int wsum[32];
    int i = blockIdx.x * SCAN_TPB + threadIdx.x;
    int v = (i < n) ? g_deg[i] : 0;
    int total;
    block_scan_1024(v, &total, wsum);
    if (threadIdx.x == 0) g_bsum[blockIdx.x] = total;
}

// ---- K3b: scan the 98 block sums (single small block) ----
__global__ void scan_phase2_k(int n) {
    __shared__ int wsum[32];
    __shared__ int sh[NBLK];
    int tid = threadIdx.x, lane = tid & 31, w = tid >> 5;
    int v = (tid < NBLK) ? g_bsum[tid] : 0;
    int x = v;
    #pragma unroll
    for (int o = 1; o < 32; o <<= 1) {
        int y = __shfl_up_sync(0xffffffffu, x, o);
        if (lane >= o) x += y;
    }
    if (lane == 31) wsum[w] = x;
    __syncthreads();
    if (w == 0 && lane < 4) {
        int s = wsum[lane];
        #pragma unroll
        for (int o = 1; o < 4; o <<= 1) {
            int y = __shfl_up_sync(0xfu, s, o);
            if (lane >= o) s += y;
        }
        wsum[lane] = s;
    }
    __syncthreads();
    int incl = x + (w > 0 ? wsum[w - 1] : 0);
    if (tid < NBLK) sh[tid] = incl;
    __syncthreads();
    if (tid < NBLK) g_boff[tid] = (tid > 0) ? sh[tid - 1] : 0;
    if (tid == 0) g_rowstart[n] = sh[NBLK - 1];
}

// ---- K3c: local exclusive scan + block offset -> rowstart/cur; dinv ----
__global__ void scan_phase3_k(int n) {
    __shared__ int wsum[32];
    int i = blockIdx.x * SCAN_TPB + threadIdx.x;
    int v = (i < n) ? g_deg[i] : 0;
    int total;
    int incl = block_scan_1024(v, &total, wsum);
    if (i < n) {
        int excl = g_boff[blockIdx.x] + incl - v;
        g_rowstart[i] = excl;
        g_cur[i] = excl;
        g_dinv[i] = rsqrtf((float)(v + 1));    // self-loop adds 1
    }
}

// ---- K4: fill CSR (src ids bucketed by dst) ----
__global__ void fill_k(const void* __restrict__ ei, int e) {
    long long t = (long long)blockIdx.x * blockDim.x + threadIdx.x;
    if (t < e) {
        int s = edge_at(ei, t);
        int d = edge_at(ei, (long long)e + t);
        int pos = atomicAdd(&g_cur[d], 1);
        g_csr[pos] = s;
    }
}

// ---- K6: pull-mode layer-1 aggregation + fused finalize.
//          One warp per dst node; lane owns a float4 feature chunk.
//          dinv[src] is applied here (FFMA) since g_h0 is raw x@W1. ----
__global__ void pull1_k(const float* __restrict__ b1, int n) {
    int wid_g = (blockIdx.x * blockDim.x + threadIdx.x) >> 5;
    int lane = threadIdx.x & 31;
    if (wid_g >= n) return;
    int beg = g_rowstart[wid_g];
    int end = g_rowstart[wid_g + 1];
    const float4* H0 = (const float4*)g_h0;
    float di = g_dinv[wid_g];
    float4 self = H0[(size_t)wid_g * 32 + lane];         // self-loop term (x dinv[node])
    float4 acc = make_float4(self.x * di, self.y * di, self.z * di, self.w * di);
    for (int j0 = beg; j0 < end; j0 += 32) {
        int id = (j0 + lane < end) ? g_csr[j0 + lane] : 0;
        int m = min(32, end - j0);
        for (int j = 0; j < m; j++) {
            int s = __shfl_sync(0xffffffffu, id, j);
            float ds = g_dinv[s];                        // broadcast load
            float4 v = H0[(size_t)s * 32 + lane];
            acc.x = fmaf(v.x, ds, acc.x);
            acc.y = fmaf(v.y, ds, acc.y);
            acc.z = fmaf(v.z, ds, acc.z);
            acc.w = fmaf(v.w, ds, acc.w);
        }
    }
    float4 bb = ((const float4*)b1)[lane];
    acc.x = fmaxf(fmaf(acc.x, di, bb.x), 0.0f);
    acc.y = fmaxf(fmaf(acc.y, di, bb.y), 0.0f);
    acc.z = fmaxf(fmaf(acc.z, di, bb.z), 0.0f);
    acc.w = fmaxf(fmaf(acc.w, di, bb.w), 0.0f);
    ((float4*)g_h1)[(size_t)wid_g * 32 + lane] = acc;
}

// ---- K7: g_t2 = (h1 @ W2) * dinv[row] ----
__global__ void gemm2_k(const float* __restrict__ W2, int n) {
    __shared__ float ws[FDIM * F2];
    __shared__ float hs[8][FDIM];
    int tid = threadIdx.x;               // 128 threads
    #pragma unroll
    for (int i = 0; i < F2; i++) ws[i * FDIM + tid] = W2[i * FDIM + tid];
    long long r0 = (long long)blockIdx.x * 8;
    #pragma unroll
    for (int j = 0; j < 8; j++) {
        long long r = r0 + j;
        hs[j][tid] = (r < n) ? g_h1[r * FDIM + tid] : 0.0f;
    }
    __syncthreads();
    int lr = tid >> 4;                   // local row 0..7
    int c  = tid & 15;                   // col 0..15
    float acc = 0.0f;
    #pragma unroll 8
    for (int k = 0; k < FDIM; k++) acc = fmaf(hs[lr][k], ws[k * F2 + c], acc);
    long long r = r0 + lr;
    if (r < n) g_t2[r * F2 + c] = acc * g_dinv[r];
}

// ---- K8: pull-mode layer-2 aggregation + fused finalize, writes d_out.
//          Thread per (node, float4 chunk): 4 threads/node. ----
__global__ void pull2_k(const float* __restrict__ b2, float* __restrict__ out, int n) {
    int t = blockIdx.x * blockDim.x + threadIdx.x;
    if (t >= n * 4) return;
    int node = t >> 2, q = t & 3;
    int beg = g_rowstart[node];
    int end = g_rowstart[node + 1];
    const float4* T2 = (const float4*)g_t2;
    float4 acc = T2[(size_t)node * 4 + q];               // self-loop term
    for (int j = beg; j < end; j++) {
        int s = g_csr[j];
        float4 v = T2[(size_t)s * 4 + q];
        acc.x += v.x; acc.y += v.y; acc.z += v.z; acc.w += v.w;
    }
    float di = g_dinv[node];
    float4 bb = ((const float4*)b2)[q];
    acc.x = fmaf(acc.x, di, bb.x);
    acc.y = fmaf(acc.y, di, bb.y);
    acc.z = fmaf(acc.z, di, bb.z);
    acc.w = fmaf(acc.w, di, bb.w);
    ((float4*)out)[(size_t)node * 4 + q] = acc;
}

extern "C" void kernel_launch(void* const* d_in, const int* in_sizes, int n_in,
                              void* d_out, int out_size) {
    const float* x  = (const float*)d_in[0];
    const void*  ei = d_in[1];
    const float* W1 = (const float*)d_in[2];
    const float* b1 = (const float*)d_in[3];
    const float* W2 = (const float*)d_in[4];
    const float* b2 = (const float*)d_in[5];
    float* out = (float*)d_out;

    int n = in_sizes[0] / FDIM;   // 100000
    int e = in_sizes[1] / 2;      // 1600000

    const int ws_bytes = FDIM * WS_STRIDE * sizeof(float);  // 69632
    cudaFuncSetAttribute(histgemm_k, cudaFuncAttributeMaxDynamicSharedMemorySize, ws_bytes);

    zero_probe_k<<<(n + 255) / 256, 256>>>((const unsigned long long*)ei, n);

    int gemm_blocks = (n + 127) / 128;           // 782
    int hist_blocks = (e + 255) / 256;           // 6250
    histgemm_k<<<gemm_blocks + hist_blocks, 256, ws_bytes>>>(x, W1, ei, n, e, gemm_blocks);

    int nblk = (n + SCAN_TPB - 1) / SCAN_TPB;
    scan_phase1_k<<<nblk, SCAN_TPB>>>(n);
    scan_phase2_k<<<1, 128>>>(n);
    scan_phase3_k<<<nblk, SCAN_TPB>>>(n);

    fill_k<<<(e + 255) / 256, 256>>>(ei, e);

    long long w1t = (long long)n * 32;   // one warp per node
    pull1_k<<<(unsigned)((w1t + 255) / 256), 256>>>(b1, n);

    gemm2_k<<<(n + 7) / 8, 128>>>(W2, n);

    long long p2t = (long long)n * 4;    // 4 threads per node
    pull2_k<<<(unsigned)((p2t + 255) / 256), 256>>>(b2, out, n);
}

// round 7
// speedup vs baseline: 1.0685x; 1.0685x over previous
#include <cuda_runtime.h>
#include <cuda_fp16.h>

#define FDIM 128
#define F2   16
#define NMAX 100000
#define EMAX 1600000
#define SCAN_TPB 1024
#define NBLK ((NMAX + SCAN_TPB - 1) / SCAN_TPB)   // 98
#define WS_STRIDE 136                              // W smem row stride (conflict-free B frags)

// ---- device scratch (static allocation; no cudaMalloc allowed) ----
__device__ float  g_dinv[NMAX];                  // deg^{-1/2}
__device__ int    g_deg[NMAX];                   // in-degree histogram (per-launch zeroed)
__device__ int    g_rowstart[NMAX + 1];          // CSR row offsets (by dst)
__device__ int    g_cur[NMAX];                   // CSR fill cursors
__device__ int    g_csr[EMAX];                   // CSR column (src) indices
__device__ int    g_bsum[NBLK];                  // per-block degree sums
__device__ int    g_boff[NBLK];                  // exclusive block offsets
__device__ __half g_h0[(size_t)NMAX * FDIM];     // raw x@W1, fp16 (halves gather traffic)
__device__ float  g_h1[(size_t)NMAX * FDIM];     // relu(aggregated layer 1)
__device__ float  g_t2[(size_t)NMAX * F2];       // (h1@W2) * dinv[row]
__device__ int    g_idx64;                       // 1 if edge_index is int64, 0 if int32

// Flag-dispatched edge read (handles int64 vs int32 edge_index).
__device__ __forceinline__ int edge_at(const void* ei, long long i) {
    if (g_idx64) return (int)((const long long*)ei)[i];
    return ((const int*)ei)[i];
}

__device__ __forceinline__ unsigned f2tf32(float f) {
    unsigned r;
    asm("cvt.rna.tf32.f32 %0, %1;" : "=r"(r) : "f"(f));
    return r;
}

__device__ __forceinline__ void mma_tf32(float* d, unsigned a0, unsigned a1,
                                         unsigned a2, unsigned a3,
                                         unsigned b0, unsigned b1) {
    asm volatile(
        "mma.sync.aligned.m16n8k8.row.col.f32.tf32.tf32.f32 "
        "{%0,%1,%2,%3}, {%4,%5,%6,%7}, {%8,%9}, {%0,%1,%2,%3};"
        : "+f"(d[0]), "+f"(d[1]), "+f"(d[2]), "+f"(d[3])
        : "r"(a0), "r"(a1), "r"(a2), "r"(a3), "r"(b0), "r"(b1));
}

// ---- K1: zero degree histogram; thread 0 probes edge dtype. ----
__global__ void zero_probe_k(const unsigned long long* __restrict__ ei, int n) {
    int i = blockIdx.x * blockDim.x + threadIdx.x;
    if (i < n) g_deg[i] = 0;
    if (i == 0) {
        int is64 = 1;
        for (int j = 0; j < 256; j++) {
            if (ei[j] >> 32) { is64 = 0; break; }
        }
        g_idx64 = is64;
    }
}

// ---- K2: in-degree histogram over dst (standalone; zero smem, full occupancy) ----
__global__ void hist_k(const void* __restrict__ ei, int e) {
    long long t = (long long)blockIdx.x * blockDim.x + threadIdx.x;
    if (t < e) {
        int d = edge_at(ei, (long long)e + t);
        atomicAdd(&g_deg[d], 1);
    }
}

// Block-wide inclusive scan of one value per thread (1024 threads, 32 warps).
__device__ __forceinline__ int block_scan_1024(int v, int* block_total, int* wsum) {
    int lane = threadIdx.x & 31, w = threadIdx.x >> 5;
    int x = v;
    #pragma unroll
    for (int o = 1; o < 32; o <<= 1) {
        int y = __shfl_up_sync(0xffffffffu, x, o);
        if (lane >= o) x += y;
    }
    if (lane == 31) wsum[w] = x;
    __syncthreads();
    if (w == 0) {
        int s = wsum[lane];
        #pragma unroll
        for (int o = 1; o < 32; o <<= 1) {
            int y = __shfl_up_sync(0xffffffffu, s, o);
            if (lane >= o) s += y;
        }
        wsum[lane] = s;
    }
    __syncthreads();
    int incl = x + (w > 0 ? wsum[w - 1] : 0);
    *block_total = wsum[31];
    return incl;
}

// ---- K3a: per-block degree sums ----
__global__ void scan_phase1_k(int n) {
    __shared__ int wsum[32];
    int i = blockIdx.x * SCAN_TPB + threadIdx.x;
    int v = (i < n) ? g_deg[i] : 0;
    int total;
    block_scan_1024(v, &total, wsum);
    if (threadIdx.x == 0) g_bsum[blockIdx.x] = total;
}

// ---- K3b: scan the 98 block sums (single small block) ----
__global__ void scan_phase2_k(int n) {
    __shared__ int wsum[32];
    __shared__ int sh[NBLK];
    int tid = threadIdx.x, lane = tid & 31, w = tid >> 5;
    int v = (tid < NBLK) ? g_bsum[tid] : 0;
    int x = v;
    #pragma unroll
    for (int o = 1; o < 32; o <<= 1) {
        int y = __shfl_up_sync(0xffffffffu, x, o);
        if (lane >= o) x += y;
    }
    if (lane == 31) wsum[w] = x;
    __syncthreads();
    if (w == 0 && lane < 4) {
        int s = wsum[lane];
        #pragma unroll
        for (int o = 1; o < 4; o <<= 1) {
            int y = __shfl_up_sync(0xfu, s, o);
            if (lane >= o) s += y;
        }
        wsum[lane] = s;
    }
    __syncthreads();
    int incl = x + (w > 0 ? wsum[w - 1] : 0);
    if (tid < NBLK) sh[tid] = incl;
    __syncthreads();
    if (tid < NBLK) g_boff[tid] = (tid > 0) ? sh[tid - 1] : 0;
    if (tid == 0) g_rowstart[n] = sh[NBLK - 1];
}

// ---- K3c: local exclusive scan + block offset -> rowstart/cur; dinv ----
__global__ void scan_phase3_k(int n) {
    __shared__ int wsum[32];
    int i = blockIdx.x * SCAN_TPB + threadIdx.x;
    int v = (i < n) ? g_deg[i] : 0;
    int total;
    int incl = block_scan_1024(v, &total, wsum);
    if (i < n) {
        int excl = g_boff[blockIdx.x] + incl - v;
        g_rowstart[i] = excl;
        g_cur[i] = excl;
        g_dinv[i] = rsqrtf((float)(v + 1));    // self-loop adds 1
    }
}

// ---- K4: fill CSR (src ids bucketed by dst) ----
__global__ void fill_k(const void* __restrict__ ei, int e) {
    long long t = (long long)blockIdx.x * blockDim.x + threadIdx.x;
    if (t < e) {
        int s = edge_at(ei, t);
        int d = edge_at(ei, (long long)e + t);
        int pos = atomicAdd(&g_cur[d], 1);
        g_csr[pos] = s;
    }
}

// ---- K5: g_h0 = x @ W1 (raw, fp16 out) via split-TF32 tensor-core MMA.
// 8 warps/block; block tile = 128 rows; warp tile = 16 rows x 128 cols. ----
__global__ void __launch_bounds__(256) gemm1_k(
        const float* __restrict__ x, const float* __restrict__ W1, int n) {
    extern __shared__ float Ws[];        // [128][WS_STRIDE]
    int tid = threadIdx.x;
    int warp = tid >> 5, lane = tid & 31;

    #pragma unroll
    for (int i = 0; i < 64; i++) {
        int idx = i * 256 + tid;         // 16384 elements of W1
        int k = idx >> 7, nn = idx & 127;
        Ws[k * WS_STRIDE + nn] = W1[idx];
    }
    __syncthreads();

    int r_base = blockIdx.x * 128 + warp * 16;
    int row_a = r_base + (lane >> 2);    // fragment row (lower 8)
    int quad  = lane & 3;

    float acc[16][4];
    #pragma unroll
    for (int nt = 0; nt < 16; nt++) {
        acc[nt][0] = acc[nt][1] = acc[nt][2] = acc[nt][3] = 0.0f;
    }

    #pragma unroll
    for (int ks = 0; ks < 16; ks++) {
        int k0 = ks * 8;
        float a0f = (row_a < n)     ? __ldg(&x[row_a * FDIM + k0 + quad])           : 0.0f;
        float a1f = (row_a + 8 < n) ? __ldg(&x[(row_a + 8) * FDIM + k0 + quad])     : 0.0f;
        float a2f = (row_a < n)     ? __ldg(&x[row_a * FDIM + k0 + 4 + quad])       : 0.0f;
        float a3f = (row_a + 8 < n) ? __ldg(&x[(row_a + 8) * FDIM + k0 + 4 + quad]) : 0.0f;
        unsigned ah0 = f2tf32(a0f), ah1 = f2tf32(a1f), ah2 = f2tf32(a2f), ah3 = f2tf32(a3f);
        unsigned al0 = f2tf32(a0f - __uint_as_float(ah0));
        unsigned al1 = f2tf32(a1f - __uint_as_float(ah1));
        unsigned al2 = f2tf32(a2f - __uint_as_float(ah2));
        unsigned al3 = f2tf32(a3f - __uint_as_float(ah3));

        const float* w0 = &Ws[(k0 + quad) * WS_STRIDE + (lane >> 2)];
        const float* w1 = &Ws[(k0 + 4 + quad) * WS_STRIDE + (lane >> 2)];
        #pragma unroll
        for (int nt = 0; nt < 16; nt++) {
            float b0f = w0[nt * 8];
            float b1f = w1[nt * 8];
            unsigned bh0 = f2tf32(b0f), bh1 = f2tf32(b1f);
            unsigned bl0 = f2tf32(b0f - __uint_as_float(bh0));
            unsigned bl1 = f2tf32(b1f - __uint_as_float(bh1));
            mma_tf32(acc[nt], ah0, ah1, ah2, ah3, bh0, bh1);
            mma_tf32(acc[nt], al0, al1, al2, al3, bh0, bh1);
            mma_tf32(acc[nt], ah0, ah1, ah2, ah3, bl0, bl1);
        }
    }

    // Epilogue: store raw result as fp16 pairs (dinv applied later in pull1).
    #pragma unroll
    for (int nt = 0; nt < 16; nt++) {
        int col = nt * 8 + quad * 2;
        if (row_a < n) {
            __half2 v = __floats2half2_rn(acc[nt][0], acc[nt][1]);
            *(__half2*)&g_h0[(size_t)row_a * FDIM + col] = v;
        }
        if (row_a + 8 < n) {
            __half2 v = __floats2half2_rn(acc[nt][2], acc[nt][3]);
            *(__half2*)&g_h0[(size_t)(row_a + 8) * FDIM + col] = v;
        }
    }
}

// ---- K6: pull-mode layer-1 aggregation + fused finalize.
//          One warp per dst node; lane owns 4 features (8B fp16 load).
//          dinv[src] applied in fp32 during the gather. ----
__global__ void pull1_k(const float* __restrict__ b1, int n) {
    int wid_g = (blockIdx.x * blockDim.x + threadIdx.x) >> 5;
    int lane = threadIdx.x & 31;
    if (wid_g >= n) return;
    int beg = g_rowstart[wid_g];
    int end = g_rowstart[wid_g + 1];
    const uint2* H0 = (const uint2*)g_h0;
    float di = g_dinv[wid_g];

    uint2 sv = H0[(size_t)wid_g * 32 + lane];            // self-loop term
    float2 s0 = __half22float2(*(const __half2*)&sv.x);
    float2 s1 = __half22float2(*(const __half2*)&sv.y);
    float4 acc = make_float4(s0.x * di, s0.y * di, s1.x * di, s1.y * di);

    for (int j0 = beg; j0 < end; j0 += 32) {
        int id = (j0 + lane < end) ? g_csr[j0 + lane] : 0;
        int m = min(32, end - j0);
        for (int j = 0; j < m; j++) {
            int s = __shfl_sync(0xffffffffu, id, j);
            float ds = g_dinv[s];                        // broadcast load
            uint2 v = H0[(size_t)s * 32 + lane];
            float2 p0 = __half22float2(*(const __half2*)&v.x);
            float2 p1 = __half22float2(*(const __half2*)&v.y);
            acc.x = fmaf(p0.x, ds, acc.x);
            acc.y = fmaf(p0.y, ds, acc.y);
            acc.z = fmaf(p1.x, ds, acc.z);
            acc.w = fmaf(p1.y, ds, acc.w);
        }
    }
    float4 bb = ((const float4*)b1)[lane];
    acc.x = fmaxf(fmaf(acc.x, di, bb.x), 0.0f);
    acc.y = fmaxf(fmaf(acc.y, di, bb.y), 0.0f);
    acc.z = fmaxf(fmaf(acc.z, di, bb.z), 0.0f);
    acc.w = fmaxf(fmaf(acc.w, di, bb.w), 0.0f);
    ((float4*)g_h1)[(size_t)wid_g * 32 + lane] = acc;
}

// ---- K7: g_t2 = (h1 @ W2) * dinv[row] ----
__global__ void gemm2_k(const float* __restrict__ W2, int n) {
    __shared__ float ws[FDIM * F2];
    __shared__ float hs[8][FDIM];
    int tid = threadIdx.x;               // 128 threads
    #pragma unroll
    for (int i = 0; i < F2; i++) ws[i * FDIM + tid] = W2[i * FDIM + tid];
    long long r0 = (long long)blockIdx.x * 8;
    #pragma unroll
    for (int j = 0; j < 8; j++) {
        long long r = r0 + j;
        hs[j][tid] = (r < n) ? g_h1[r * FDIM + tid] : 0.0f;
    }
    __syncthreads();
    int lr = tid >> 4;                   // local row 0..7
    int c  = tid & 15;                   // col 0..15
    float acc = 0.0f;
    #pragma unroll 8
    for (int k = 0; k < FDIM; k++) acc = fmaf(hs[lr][k], ws[k * F2 + c], acc);
    long long r = r0 + lr;
    if (r < n) g_t2[r * F2 + c] = acc * g_dinv[r];
}

// ---- K8: pull-mode layer-2 aggregation + fused finalize, writes d_out.
//          Thread per (node, float4 chunk): 4 threads/node. ----
__global__ void pull2_k(const float* __restrict__ b2, float* __restrict__ out, int n) {
    int t = blockIdx.x * blockDim.x + threadIdx.x;
    if (t >= n * 4) return;
    int node = t >> 2, q = t & 3;
    int beg = g_rowstart[node];
    int end = g_rowstart[node + 1];
    const float4* T2 = (const float4*)g_t2;
    float4 acc = T2[(size_t)node * 4 + q];               // self-loop term
    for (int j = beg; j < end; j++) {
        int s = g_csr[j];
        float4 v = T2[(size_t)s * 4 + q];
        acc.x += v.x; acc.y += v.y; acc.z += v.z; acc.w += v.w;
    }
    float di = g_dinv[node];
    float4 bb = ((const float4*)b2)[q];
    acc.x = fmaf(acc.x, di, bb.x);
    acc.y = fmaf(acc.y, di, bb.y);
    acc.z = fmaf(acc.z, di, bb.z);
    acc.w = fmaf(acc.w, di, bb.w);
    ((float4*)out)[(size_t)node * 4 + q] = acc;
}

extern "C" void kernel_launch(void* const* d_in, const int* in_sizes, int n_in,
                              void* d_out, int out_size) {
    const float* x  = (const float*)d_in[0];
    const void*  ei = d_in[1];
    const float* W1 = (const float*)d_in[2];
    const float* b1 = (const float*)d_in[3];
    const float* W2 = (const float*)d_in[4];
    const float* b2 = (const float*)d_in[5];
    float* out = (float*)d_out;

    int n = in_sizes[0] / FDIM;   // 100000
    int e = in_sizes[1] / 2;      // 1600000

    const int ws_bytes = FDIM * WS_STRIDE * sizeof(float);  // 69632
    cudaFuncSetAttribute(gemm1_k, cudaFuncAttributeMaxDynamicSharedMemorySize, ws_bytes);

    zero_probe_k<<<(n + 255) / 256, 256>>>((const unsigned long long*)ei, n);
    hist_k<<<(e + 255) / 256, 256>>>(ei, e);

    int nblk = (n + SCAN_TPB - 1) / SCAN_TPB;
    scan_phase1_k<<<nblk, SCAN_TPB>>>(n);
    scan_phase2_k<<<1, 128>>>(n);
    scan_phase3_k<<<nblk, SCAN_TPB>>>(n);

    fill_k<<<(e + 255) / 256, 256>>>(ei, e);

    gemm1_k<<<(n + 127) / 128, 256, ws_bytes>>>(x, W1, n);

    long long w1t = (long long)n * 32;   // one warp per node
    pull1_k<<<(unsigned)((w1t + 255) / 256), 256>>>(b1, n);

    gemm2_k<<<(n + 7) / 8, 128>>>(W2, n);

    long long p2t = (long long)n * 4;    // 4 threads per node
    pull2_k<<<(unsigned)((p2t + 255) / 256), 256>>>(b2, out, n);
}

// round 8
// speedup vs baseline: 1.1802x; 1.1046x over previous
#include <cuda_runtime.h>
#include <cuda_fp16.h>

#define FDIM 128
#define F2   16
#define NMAX 100000
#define EMAX 1600000
#define SCAN_TPB 1024
#define NBLK ((NMAX + SCAN_TPB - 1) / SCAN_TPB)   // 98
#define WS_STRIDE 136                              // W smem row stride (conflict-free B frags)

// ---- device scratch (static allocation; no cudaMalloc allowed) ----
__device__ float  g_dinv[NMAX];                  // deg^{-1/2}
__device__ int    g_deg[NMAX];                   // in-degree histogram (per-launch zeroed)
__device__ int    g_rowstart[NMAX + 1];          // CSR row offsets (by dst)
__device__ int    g_cur[NMAX];                   // CSR fill cursors
__device__ int    g_csr[EMAX];                   // CSR column (src) indices
__device__ int    g_bsum[NBLK];                  // per-block degree sums
__device__ __half g_h0[(size_t)NMAX * FDIM];     // (x@W1)*dinv[row], fp16
__device__ float  g_h1[(size_t)NMAX * FDIM];     // relu(aggregated layer 1)
__device__ float  g_t2[(size_t)NMAX * F2];       // (h1@W2) * dinv[row]
__device__ int    g_idx64;                       // 1 if edge_index is int64, 0 if int32

// Flag-dispatched edge read (handles int64 vs int32 edge_index).
__device__ __forceinline__ int edge_at(const void* ei, long long i) {
    if (g_idx64) return (int)((const long long*)ei)[i];
    return ((const int*)ei)[i];
}

__device__ __forceinline__ unsigned f2tf32(float f) {
    unsigned r;
    asm("cvt.rna.tf32.f32 %0, %1;" : "=r"(r) : "f"(f));
    return r;
}

__device__ __forceinline__ void mma_tf32(float* d, unsigned a0, unsigned a1,
                                         unsigned a2, unsigned a3,
                                         unsigned b0, unsigned b1) {
    asm volatile(
        "mma.sync.aligned.m16n8k8.row.col.f32.tf32.tf32.f32 "
        "{%0,%1,%2,%3}, {%4,%5,%6,%7}, {%8,%9}, {%0,%1,%2,%3};"
        : "+f"(d[0]), "+f"(d[1]), "+f"(d[2]), "+f"(d[3])
        : "r"(a0), "r"(a1), "r"(a2), "r"(a3), "r"(b0), "r"(b1));
}

// ---- K1: zero degree histogram; warp 0 of block 0 probes edge dtype in
// parallel (32 lanes x 8 samples + __any_sync; no serial dependent loads). ----
__global__ void zero_probe_k(const unsigned long long* __restrict__ ei, int n) {
    int i = blockIdx.x * blockDim.x + threadIdx.x;
    if (i < n) g_deg[i] = 0;
    if (blockIdx.x == 0 && threadIdx.x < 32) {
        unsigned long long hi = 0;
        #pragma unroll
        for (int j = 0; j < 8; j++) hi |= ei[threadIdx.x + j * 32] >> 32;
        int any = __any_sync(0xffffffffu, hi != 0);
        if (threadIdx.x == 0) g_idx64 = any ? 0 : 1;
    }
}

// ---- K2: in-degree histogram over dst ----
__global__ void hist_k(const void* __restrict__ ei, int e) {
    long long t = (long long)blockIdx.x * blockDim.x + threadIdx.x;
    if (t < e) {
        int d = edge_at(ei, (long long)e + t);
        atomicAdd(&g_deg[d], 1);
    }
}

// Block-wide inclusive scan of one value per thread (1024 threads, 32 warps).
__device__ __forceinline__ int block_scan_1024(int v, int* block_total, int* wsum) {
    int lane = threadIdx.x & 31, w = threadIdx.x >> 5;
    int x = v;
    #pragma unroll
    for (int o = 1; o < 32; o <<= 1) {
        int y = __shfl_up_sync(0xffffffffu, x, o);
        if (lane >= o) x += y;
    }
    if (lane == 31) wsum[w] = x;
    __syncthreads();
    if (w == 0) {
        int s = wsum[lane];
        #pragma unroll
        for (int o = 1; o < 32; o <<= 1) {
            int y = __shfl_up_sync(0xffffffffu, s, o);
            if (lane >= o) s += y;
        }
        wsum[lane] = s;
    }
    __syncthreads();
    int incl = x + (w > 0 ? wsum[w - 1] : 0);
    *block_total = wsum[31];
    return incl;
}

// ---- K3a: per-block degree sums ----
__global__ void scan_phase1_k(int n) {
    __shared__ int wsum[32];
    int i = blockIdx.x * SCAN_TPB + threadIdx.x;
    int v = (i < n) ? g_deg[i] : 0;
    int total;
    block_scan_1024(v, &total, wsum);
    if (threadIdx.x == 0) g_bsum[blockIdx.x] = total;
}

// ---- K3b: local scan; each block computes its own prefix over g_bsum
// (<=97 values, one warp-reduce) -> no separate phase-2 kernel. ----
__global__ void scan_phase3_k(int n) {
    __shared__ int wsum[32];
    __shared__ int s_boff;
    if (threadIdx.x < 32) {
        int sum = 0;
        for (int j = threadIdx.x; j < blockIdx.x; j += 32) sum += g_bsum[j];
        #pragma unroll
        for (int o = 16; o > 0; o >>= 1) sum += __shfl_down_sync(0xffffffffu, sum, o);
        if (threadIdx.x == 0) s_boff = sum;
    }
    int i = blockIdx.x * SCAN_TPB + threadIdx.x;
    int v = (i < n) ? g_deg[i] : 0;
    int total;
    int incl = block_scan_1024(v, &total, wsum);   // includes the needed __syncthreads
    int boff = s_boff;
    if (i < n) {
        int excl = boff + incl - v;
        g_rowstart[i] = excl;
        g_cur[i] = excl;
        g_dinv[i] = rsqrtf((float)(v + 1));        // self-loop adds 1
    }
    if (blockIdx.x == gridDim.x - 1 && threadIdx.x == 0)
        g_rowstart[n] = boff + total;
}

// ---- K4: fill CSR (src ids bucketed by dst) ----
__global__ void fill_k(const void* __restrict__ ei, int e) {
    long long t = (long long)blockIdx.x * blockDim.x + threadIdx.x;
    if (t < e) {
        int s = edge_at(ei, t);
        int d = edge_at(ei, (long long)e + t);
        int pos = atomicAdd(&g_cur[d], 1);
        g_csr[pos] = s;
    }
}

// ---- K5: g_h0 = (x @ W1) * dinv[row] (fp16 out) via split-TF32 MMA.
// 8 warps/block; block tile = 128 rows; warp tile = 16 rows x 128 cols. ----
__global__ void __launch_bounds__(256) gemm1_k(
        const float* __restrict__ x, const float* __restrict__ W1, int n) {
    extern __shared__ float Ws[];        // [128][WS_STRIDE]
    int tid = threadIdx.x;
    int warp = tid >> 5, lane = tid & 31;

    #pragma unroll
    for (int i = 0; i < 64; i++) {
        int idx = i * 256 + tid;         // 16384 elements of W1
        int k = idx >> 7, nn = idx & 127;
        Ws[k * WS_STRIDE + nn] = W1[idx];
    }
    __syncthreads();

    int r_base = blockIdx.x * 128 + warp * 16;
    int row_a = r_base + (lane >> 2);    // fragment row (lower 8)
    int quad  = lane & 3;

    float acc[16][4];
    #pragma unroll
    for (int nt = 0; nt < 16; nt++) {
        acc[nt][0] = acc[nt][1] = acc[nt][2] = acc[nt][3] = 0.0f;
    }

    #pragma unroll
    for (int ks = 0; ks < 16; ks++) {
        int k0 = ks * 8;
        float a0f = (row_a < n)     ? __ldg(&x[row_a * FDIM + k0 + quad])           : 0.0f;
        float a1f = (row_a + 8 < n) ? __ldg(&x[(row_a + 8) * FDIM + k0 + quad])     : 0.0f;
        float a2f = (row_a < n)     ? __ldg(&x[row_a * FDIM + k0 + 4 + quad])       : 0.0f;
        float a3f = (row_a + 8 < n) ? __ldg(&x[(row_a + 8) * FDIM + k0 + 4 + quad]) : 0.0f;
        unsigned ah0 = f2tf32(a0f), ah1 = f2tf32(a1f), ah2 = f2tf32(a2f), ah3 = f2tf32(a3f);
        unsigned al0 = f2tf32(a0f - __uint_as_float(ah0));
        unsigned al1 = f2tf32(a1f - __uint_as_float(ah1));
        unsigned al2 = f2tf32(a2f - __uint_as_float(ah2));
        unsigned al3 = f2tf32(a3f - __uint_as_float(ah3));

        const float* w0 = &Ws[(k0 + quad) * WS_STRIDE + (lane >> 2)];
        const float* w1 = &Ws[(k0 + 4 + quad) * WS_STRIDE + (lane >> 2)];
        #pragma unroll
        for (int nt = 0; nt < 16; nt++) {
            float b0f = w0[nt * 8];
            float b1f = w1[nt * 8];
            unsigned bh0 = f2tf32(b0f), bh1 = f2tf32(b1f);
            unsigned bl0 = f2tf32(b0f - __uint_as_float(bh0));
            unsigned bl1 = f2tf32(b1f - __uint_as_float(bh1));
            mma_tf32(acc[nt], ah0, ah1, ah2, ah3, bh0, bh1);
            mma_tf32(acc[nt], al0, al1, al2, al3, bh0, bh1);
            mma_tf32(acc[nt], ah0, ah1, ah2, ah3, bl0, bl1);
        }
    }

    // Epilogue: scale by dinv[row], store fp16 pairs.
    float di0 = (row_a < n)     ? g_dinv[row_a]     : 0.0f;
    float di1 = (row_a + 8 < n) ? g_dinv[row_a + 8] : 0.0f;
    #pragma unroll
    for (int nt = 0; nt < 16; nt++) {
        int col = nt * 8 + quad * 2;
        if (row_a < n) {
            __half2 v = __floats2half2_rn(acc[nt][0] * di0, acc[nt][1] * di0);
            *(__half2*)&g_h0[(size_t)row_a * FDIM + col] = v;
        }
        if (row_a + 8 < n) {
            __half2 v = __floats2half2_rn(acc[nt][2] * di1, acc[nt][3] * di1);
            *(__half2*)&g_h0[(size_t)(row_a + 8) * FDIM + col] = v;
        }
    }
}

// ---- K6: pull-mode layer-1 aggregation + fused finalize.
//          One warp per dst node; lane owns 4 features (8B fp16 load).
//          Neighbor id is a warp-uniform broadcast load; unroll 4 -> MLP 4. ----
__global__ void pull1_k(const float* __restrict__ b1, int n) {
    int wid_g = (blockIdx.x * blockDim.x + threadIdx.x) >> 5;
    int lane = threadIdx.x & 31;
    if (wid_g >= n) return;
    int beg = g_rowstart[wid_g];
    int end = g_rowstart[wid_g + 1];
    const uint2* H0 = (const uint2*)g_h0;

    uint2 sv = H0[(size_t)wid_g * 32 + lane];            // self-loop term
    float2 s0 = __half22float2(*(const __half2*)&sv.x);
    float2 s1 = __half22float2(*(const __half2*)&sv.y);
    float4 acc = make_float4(s0.x, s0.y, s1.x, s1.y);

    #pragma unroll 4
    for (int j = beg; j < end; j++) {
        int s = __ldg(&g_csr[j]);                        // warp-uniform broadcast
        uint2 v = H0[(size_t)s * 32 + lane];
        float2 p0 = __half22float2(*(const __half2*)&v.x);
        float2 p1 = __half22float2(*(const __half2*)&v.y);
        acc.x += p0.x; acc.y += p0.y; acc.z += p1.x; acc.w += p1.y;
    }
    float di = g_dinv[wid_g];
    float4 bb = ((const float4*)b1)[lane];
    acc.x = fmaxf(fmaf(acc.x, di, bb.x), 0.0f);
    acc.y = fmaxf(fmaf(acc.y, di, bb.y), 0.0f);
    acc.z = fmaxf(fmaf(acc.z, di, bb.z), 0.0f);
    acc.w = fmaxf(fmaf(acc.w, di, bb.w), 0.0f);
    ((float4*)g_h1)[(size_t)wid_g * 32 + lane] = acc;
}

// ---- K7: g_t2 = (h1 @ W2) * dinv[row] ----
__global__ void gemm2_k(const float* __restrict__ W2, int n) {
    __shared__ float ws[FDIM * F2];
    __shared__ float hs[8][FDIM];
    int tid = threadIdx.x;               // 128 threads
    #pragma unroll
    for (int i = 0; i < F2; i++) ws[i * FDIM + tid] = W2[i * FDIM + tid];
    long long r0 = (long long)blockIdx.x * 8;
    #pragma unroll
    for (int j = 0; j < 8; j++) {
        long long r = r0 + j;
        hs[j][tid] = (r < n) ? g_h1[r * FDIM + tid] : 0.0f;
    }
    __syncthreads();
    int lr = tid >> 4;                   // local row 0..7
    int c  = tid & 15;                   // col 0..15
    float acc = 0.0f;
    #pragma unroll 8
    for (int k = 0; k < FDIM; k++) acc = fmaf(hs[lr][k], ws[k * F2 + c], acc);
    long long r = r0 + lr;
    if (r < n) g_t2[r * F2 + c] = acc * g_dinv[r];
}

// ---- K8: pull-mode layer-2 aggregation + fused finalize, writes d_out.
//          Thread per (node, float4 chunk): 4 threads/node. ----
__global__ void pull2_k(const float* __restrict__ b2, float* __restrict__ out, int n) {
    int t = blockIdx.x * blockDim.x + threadIdx.x;
    if (t >= n * 4) return;
    int node = t >> 2, q = t & 3;
    int beg = g_rowstart[node];
    int end = g_rowstart[node + 1];
    const float4* T2 = (const float4*)g_t2;
    float4 acc = T2[(size_t)node * 4 + q];               // self-loop term
    #pragma unroll 4
    for (int j = beg; j < end; j++) {
        int s = __ldg(&g_csr[j]);
        float4 v = T2[(size_t)s * 4 + q];
        acc.x += v.x; acc.y += v.y; acc.z += v.z; acc.w += v.w;
    }
    float di = g_dinv[node];
    float4 bb = ((const float4*)b2)[q];
    acc.x = fmaf(acc.x, di, bb.x);
    acc.y = fmaf(acc.y, di, bb.y);
    acc.z = fmaf(acc.z, di, bb.z);
    acc.w = fmaf(acc.w, di, bb.w);
    ((float4*)out)[(size_t)node * 4 + q] = acc;
}

extern "C" void kernel_launch(void* const* d_in, const int* in_sizes, int n_in,
                              void* d_out, int out_size) {
    const float* x  = (const float*)d_in[0];
    const void*  ei = d_in[1];
    const float* W1 = (const float*)d_in[2];
    const float* b1 = (const float*)d_in[3];
    const float* W2 = (const float*)d_in[4];
    const float* b2 = (const float*)d_in[5];
    float* out = (float*)d_out;

    int n = in_sizes[0] / FDIM;   // 100000
    int e = in_sizes[1] / 2;      // 1600000

    const int ws_bytes = FDIM * WS_STRIDE * sizeof(float);  // 69632
    cudaFuncSetAttribute(gemm1_k, cudaFuncAttributeMaxDynamicSharedMemorySize, ws_bytes);

    int nblk = (n + SCAN_TPB - 1) / SCAN_TPB;

    zero_probe_k<<<(n + 255) / 256, 256>>>((const unsigned long long*)ei, n);  // 1
    hist_k<<<(e + 255) / 256, 256>>>(ei, e);                                   // 2
    scan_phase1_k<<<nblk, SCAN_TPB>>>(n);                                      // 3
    scan_phase3_k<<<nblk, SCAN_TPB>>>(n);                                      // 4
    fill_k<<<(e + 255) / 256, 256>>>(ei, e);                                   // 5
    gemm1_k<<<(n + 127) / 128, 256, ws_bytes>>>(x, W1, n);                     // 6 <- ncu capture

    long long w1t = (long long)n * 32;   // one warp per node
    pull1_k<<<(unsigned)((w1t + 255) / 256), 256>>>(b1, n);                    // 7

    gemm2_k<<<(n + 7) / 8, 128>>>(W2, n);                                      // 8

    long long p2t = (long long)n * 4;    // 4 threads per node
    pull2_k<<<(unsigned)((p2t + 255) / 256), 256>>>(b2, out, n);               // 9
}